// round 2
// baseline (speedup 1.0000x reference)
#include <cuda_runtime.h>
#include <cuda_fp16.h>
#include <cstdint>

// Problem constants
#define N_ROWS 16384
#define KNB    25
#define DIM    512
#define ODIM   1024

// GEMM tiling
#define BM 128
#define BN 128
#define BK 32
#define SROW 40            // smem row stride in halves (80 bytes) -> conflict-free ldmatrix

// Scratch (device globals — no allocation allowed)
__device__ __half g_A [N_ROWS * DIM];   // fp16 means, [N, D] row-major
__device__ __half g_WT[ODIM  * DIM];    // fp16 W^T,   [O, D] K-major (col-major B operand)

// ---------------------------------------------------------------------------
// Kernel 1: W[D,O] -> fp16 transposed [O, D]
// ---------------------------------------------------------------------------
__global__ void __launch_bounds__(256) wprep_kernel(const float* __restrict__ W)
{
    int idx = blockIdx.x * 256 + threadIdx.x;   // 512*1024 total
    int k = idx >> 10;
    int o = idx & 1023;
    g_WT[o * DIM + k] = __float2half_rn(W[idx]);
}

// ---------------------------------------------------------------------------
// Kernel 2: means = (sum_k neigh[n,k,:] + self[n,:]) / 26  -> fp16
// ---------------------------------------------------------------------------
__global__ void __launch_bounds__(128) mean_kernel(const float* __restrict__ self_vecs,
                                                   const float* __restrict__ neigh)
{
    int n = blockIdx.x;
    int t = threadIdx.x;
    const float4* sv = (const float4*)(self_vecs) + (size_t)n * (DIM / 4);
    const float4* nv = (const float4*)(neigh)     + (size_t)n * KNB * (DIM / 4);

    float4 acc = sv[t];
    #pragma unroll
    for (int k = 0; k < KNB; k++) {
        float4 v = nv[k * (DIM / 4) + t];
        acc.x += v.x; acc.y += v.y; acc.z += v.z; acc.w += v.w;
    }
    const float inv = 1.0f / (float)(KNB + 1);
    acc.x *= inv; acc.y *= inv; acc.z *= inv; acc.w *= inv;

    __half2* out = (__half2*)g_A + (size_t)n * (DIM / 2);
    out[t * 2 + 0] = __floats2half2_rn(acc.x, acc.y);
    out[t * 2 + 1] = __floats2half2_rn(acc.z, acc.w);
}

// ---------------------------------------------------------------------------
// mma.sync helpers
// ---------------------------------------------------------------------------
__device__ __forceinline__ uint32_t smem_addr32(const void* p) {
    return (uint32_t)__cvta_generic_to_shared(p);
}

__device__ __forceinline__ void ldmatrix_x4(uint32_t& r0, uint32_t& r1,
                                            uint32_t& r2, uint32_t& r3, uint32_t addr) {
    asm volatile("ldmatrix.sync.aligned.m8n8.x4.shared.b16 {%0,%1,%2,%3}, [%4];"
                 : "=r"(r0), "=r"(r1), "=r"(r2), "=r"(r3) : "r"(addr));
}

__device__ __forceinline__ void mma16816(float* c, const uint32_t* a, const uint32_t* b) {
    asm volatile(
        "mma.sync.aligned.m16n8k16.row.col.f32.f16.f16.f32 "
        "{%0,%1,%2,%3}, {%4,%5,%6,%7}, {%8,%9}, {%0,%1,%2,%3};"
        : "+f"(c[0]), "+f"(c[1]), "+f"(c[2]), "+f"(c[3])
        : "r"(a[0]), "r"(a[1]), "r"(a[2]), "r"(a[3]), "r"(b[0]), "r"(b[1]));
}

__device__ __forceinline__ void cp_async16(uint32_t dst, const void* src) {
    asm volatile("cp.async.cg.shared.global [%0], [%1], 16;" :: "r"(dst), "l"(src));
}

// ---------------------------------------------------------------------------
// Kernel 3: out = relu(A_fp16 @ WT_fp16^T + b), fp32 accumulate
// 256 threads = 8 warps arranged 4(m) x 2(n); warp tile 32x64.
// ---------------------------------------------------------------------------
__global__ void __launch_bounds__(256) gemm_kernel(const float* __restrict__ bias,
                                                   float* __restrict__ out)
{
    __shared__ __half sA[2][BM * SROW];
    __shared__ __half sB[2][BN * SROW];

    int tid = threadIdx.x;
    int wid = tid >> 5;
    int lane = tid & 31;
    int warp_m = wid & 3;       // 0..3 -> 32-row slice
    int warp_n = wid >> 2;      // 0..1 -> 64-col slice
    int m0 = blockIdx.x * BM;
    int n0 = blockIdx.y * BN;

    // per-thread cp.async source/dest (2 16B chunks per tile per thread)
    // idx = tid + j*256; row = idx>>2 (0..127), c = idx&3 (16B chunk in 64B row)
    const __half* gA = g_A  + (size_t)m0 * DIM;
    const __half* gB = g_WT + (size_t)n0 * DIM;

    float acc[2][8][4];
    #pragma unroll
    for (int i = 0; i < 2; i++)
        #pragma unroll
        for (int j = 0; j < 8; j++)
            #pragma unroll
            for (int v = 0; v < 4; v++) acc[i][j][v] = 0.0f;

    uint32_t sA_base[2] = { smem_addr32(sA[0]), smem_addr32(sA[1]) };
    uint32_t sB_base[2] = { smem_addr32(sB[0]), smem_addr32(sB[1]) };

    // ldmatrix source addresses (fixed per thread, per k-step)
    // A: row = warp_m*32 + mt*16 + (lane&15), col halves = ks*16 + ((lane>>4)<<3)
    int a_row = warp_m * 32 + (lane & 15);
    int a_colb = ((lane >> 4) << 3);
    // B: quad = lane>>3; n = warp_n*64 + ntp*16 + ((quad>>1)<<3) + (lane&7);
    //    k = ks*16 + ((quad&1)<<3)
    int quad = lane >> 3;
    int b_row_off = ((quad >> 1) << 3) + (lane & 7);
    int b_colb = ((quad & 1) << 3);

    // prefetch stage 0
    {
        #pragma unroll
        for (int j = 0; j < 2; j++) {
            int idx = tid + j * 256;
            int row = idx >> 2, c = idx & 3;
            cp_async16(sA_base[0] + (row * SROW + c * 8) * 2, gA + (size_t)row * DIM + c * 8);
            cp_async16(sB_base[0] + (row * SROW + c * 8) * 2, gB + (size_t)row * DIM + c * 8);
        }
        asm volatile("cp.async.commit_group;");
    }

    const int NKT = DIM / BK;   // 16
    for (int kt = 0; kt < NKT; kt++) {
        asm volatile("cp.async.wait_group 0;");
        __syncthreads();

        if (kt + 1 < NKT) {
            int buf = (kt + 1) & 1;
            int kb = (kt + 1) * BK;
            #pragma unroll
            for (int j = 0; j < 2; j++) {
                int idx = tid + j * 256;
                int row = idx >> 2, c = idx & 3;
                cp_async16(sA_base[buf] + (row * SROW + c * 8) * 2,
                           gA + (size_t)row * DIM + kb + c * 8);
                cp_async16(sB_base[buf] + (row * SROW + c * 8) * 2,
                           gB + (size_t)row * DIM + kb + c * 8);
            }
            asm volatile("cp.async.commit_group;");
        }

        int buf = kt & 1;
        #pragma unroll
        for (int ks = 0; ks < 2; ks++) {
            // A fragments: 2 m-tiles
            uint32_t af[2][4];
            #pragma unroll
            for (int mt = 0; mt < 2; mt++) {
                uint32_t addr = sA_base[buf] +
                    ((a_row + mt * 16) * SROW + ks * 16 + a_colb) * 2;
                ldmatrix_x4(af[mt][0], af[mt][1], af[mt][2], af[mt][3], addr);
            }
            // B fragments: 8 n-tiles via 4 x4 loads (2 tiles each)
            uint32_t bf[8][2];
            #pragma unroll
            for (int ntp = 0; ntp < 4; ntp++) {
                uint32_t r0, r1, r2, r3;
                uint32_t addr = sB_base[buf] +
                    ((warp_n * 64 + ntp * 16 + b_row_off) * SROW + ks * 16 + b_colb) * 2;
                ldmatrix_x4(r0, r1, r2, r3, addr);
                bf[ntp * 2 + 0][0] = r0; bf[ntp * 2 + 0][1] = r1;
                bf[ntp * 2 + 1][0] = r2; bf[ntp * 2 + 1][1] = r3;
            }
            #pragma unroll
            for (int mt = 0; mt < 2; mt++)
                #pragma unroll
                for (int nt = 0; nt < 8; nt++)
                    mma16816(acc[mt][nt], af[mt], bf[nt]);
        }
        __syncthreads();
    }

    // Epilogue: direct fragment stores with bias + ReLU.
    // c0,c1 -> (row = lane>>2, col = 2*(lane&3)); c2,c3 -> row+8.
    #pragma unroll
    for (int nt = 0; nt < 8; nt++) {
        int col = n0 + warp_n * 64 + nt * 8 + ((lane & 3) << 1);
        float b0 = bias[col], b1 = bias[col + 1];
        #pragma unroll
        for (int mt = 0; mt < 2; mt++) {
            int row = m0 + warp_m * 32 + mt * 16 + (lane >> 2);
            float2 v0, v1;
            v0.x = fmaxf(acc[mt][nt][0] + b0, 0.0f);
            v0.y = fmaxf(acc[mt][nt][1] + b1, 0.0f);
            v1.x = fmaxf(acc[mt][nt][2] + b0, 0.0f);
            v1.y = fmaxf(acc[mt][nt][3] + b1, 0.0f);
            *(float2*)(out + (size_t)row * ODIM + col) = v0;
            *(float2*)(out + (size_t)(row + 8) * ODIM + col) = v1;
        }
    }
}

// ---------------------------------------------------------------------------
// Launch
// ---------------------------------------------------------------------------
extern "C" void kernel_launch(void* const* d_in, const int* in_sizes, int n_in,
                              void* d_out, int out_size)
{
    const float* self_vecs = (const float*)d_in[0];   // [16384, 512]
    const float* neigh     = (const float*)d_in[1];   // [16384, 25, 512]
    // d_in[2] = temperature (unused by reference)
    const float* W         = (const float*)d_in[3];   // [512, 1024]
    const float* b         = (const float*)d_in[4];   // [1024]
    float* out = (float*)d_out;                       // [16384, 1024]

    wprep_kernel<<<(ODIM * DIM) / 256, 256>>>(W);
    mean_kernel<<<N_ROWS, 128>>>(self_vecs, neigh);
    dim3 gg(N_ROWS / BM, ODIM / BN);
    gemm_kernel<<<gg, 256>>>(b, out);
}

// round 5
// speedup vs baseline: 1.0480x; 1.0480x over previous
#include <cuda_runtime.h>
#include <cuda_fp16.h>
#include <cstdint>

// Problem constants
#define N_ROWS 16384
#define KNB    25
#define DIM    512
#define ODIM   1024

// GEMM tiling
#define BM 128
#define BN 128
#define BK 32
#define SROW 40            // smem row stride in halves (80B): ldmatrix conflict-free
#define STAGES 3
#define NKT (DIM / BK)     // 16

#define TILE_HALVES (BM * SROW)                    // 5120 halves per tile
#define SMEM_BYTES  (STAGES * 2 * TILE_HALVES * 2) // 61440 bytes

// Scratch (device globals — no allocation allowed)
__device__ __half g_A [N_ROWS * DIM];   // fp16 means, [N, D] row-major
__device__ __half g_WT[ODIM  * DIM];    // fp16 W^T,   [O, D] K-major (col-major B operand)

// ---------------------------------------------------------------------------
// Kernel 1: W[D=512, O=1024] fp32 -> g_WT[O, D] fp16, tiled smem transpose.
// ---------------------------------------------------------------------------
__global__ void __launch_bounds__(256) wprep_kernel(const float* __restrict__ W)
{
    __shared__ __half s[64 * 65];
    int bk = blockIdx.x & 7;     // 8 k-tiles (512/64)
    int bo = blockIdx.x >> 3;    // 16 o-tiles (1024/64)
    int tid = threadIdx.x;

    #pragma unroll
    for (int i = 0; i < 16; i++) {
        int idx = tid + i * 256;
        int kk = idx >> 6, oo = idx & 63;
        s[kk * 65 + oo] = __float2half_rn(W[(size_t)(bk * 64 + kk) * ODIM + bo * 64 + oo]);
    }
    __syncthreads();
    #pragma unroll
    for (int i = 0; i < 16; i++) {
        int idx = tid + i * 256;
        int oo = idx >> 6, kk = idx & 63;
        g_WT[(size_t)(bo * 64 + oo) * DIM + bk * 64 + kk] = s[kk * 65 + oo];
    }
}

// ---------------------------------------------------------------------------
// Kernel 2: means = (sum_k neigh[n,k,:] + self[n,:]) / 26  -> fp16
// ---------------------------------------------------------------------------
__global__ void __launch_bounds__(128) mean_kernel(const float* __restrict__ self_vecs,
                                                   const float* __restrict__ neigh)
{
    int n = blockIdx.x;
    int t = threadIdx.x;
    const float4* sv = (const float4*)(self_vecs) + (size_t)n * (DIM / 4);
    const float4* nv = (const float4*)(neigh)     + (size_t)n * KNB * (DIM / 4);

    float4 acc = sv[t];
    #pragma unroll
    for (int k = 0; k < KNB; k++) {
        float4 v = nv[k * (DIM / 4) + t];
        acc.x += v.x; acc.y += v.y; acc.z += v.z; acc.w += v.w;
    }
    const float inv = 1.0f / (float)(KNB + 1);
    acc.x *= inv; acc.y *= inv; acc.z *= inv; acc.w *= inv;

    __half2* out = (__half2*)g_A + (size_t)n * (DIM / 2);
    out[t * 2 + 0] = __floats2half2_rn(acc.x, acc.y);
    out[t * 2 + 1] = __floats2half2_rn(acc.z, acc.w);
}

// ---------------------------------------------------------------------------
// mma.sync helpers
// ---------------------------------------------------------------------------
__device__ __forceinline__ uint32_t smem_addr32(const void* p) {
    return (uint32_t)__cvta_generic_to_shared(p);
}

__device__ __forceinline__ void ldmatrix_x4(uint32_t& r0, uint32_t& r1,
                                            uint32_t& r2, uint32_t& r3, uint32_t addr) {
    asm volatile("ldmatrix.sync.aligned.m8n8.x4.shared.b16 {%0,%1,%2,%3}, [%4];"
                 : "=r"(r0), "=r"(r1), "=r"(r2), "=r"(r3) : "r"(addr));
}

__device__ __forceinline__ void mma16816(float* c, const uint32_t* a, const uint32_t* b) {
    asm volatile(
        "mma.sync.aligned.m16n8k16.row.col.f32.f16.f16.f32 "
        "{%0,%1,%2,%3}, {%4,%5,%6,%7}, {%8,%9}, {%0,%1,%2,%3};"
        : "+f"(c[0]), "+f"(c[1]), "+f"(c[2]), "+f"(c[3])
        : "r"(a[0]), "r"(a[1]), "r"(a[2]), "r"(a[3]), "r"(b[0]), "r"(b[1]));
}

__device__ __forceinline__ void cp_async16(uint32_t dst, const void* src) {
    asm volatile("cp.async.cg.shared.global [%0], [%1], 16;" :: "r"(dst), "l"(src));
}

// ---------------------------------------------------------------------------
// Kernel 3: out = relu(A_fp16 @ WT_fp16^T + b), fp32 accumulate
// 256 threads = 8 warps (4m x 2n), warp tile 32x64.
// 3-stage cp.async ring (dynamic smem), one __syncthreads per k-tile.
// ---------------------------------------------------------------------------
__global__ void __launch_bounds__(256, 2) gemm_kernel(const float* __restrict__ bias,
                                                      float* __restrict__ out)
{
    extern __shared__ __half smem_dyn[];
    // layout: [STAGES][A tile], then [STAGES][B tile]
    int tid = threadIdx.x;
    int wid = tid >> 5;
    int lane = tid & 31;
    int warp_m = wid & 3;       // 0..3 -> 32-row slice
    int warp_n = wid >> 2;      // 0..1 -> 64-col slice
    int m0 = blockIdx.x * BM;
    int n0 = blockIdx.y * BN;

    const __half* gA = g_A  + (size_t)m0 * DIM;
    const __half* gB = g_WT + (size_t)n0 * DIM;

    float acc[2][8][4];
    #pragma unroll
    for (int i = 0; i < 2; i++)
        #pragma unroll
        for (int j = 0; j < 8; j++)
            #pragma unroll
            for (int v = 0; v < 4; v++) acc[i][j][v] = 0.0f;

    uint32_t sA_base[STAGES], sB_base[STAGES];
    uint32_t sdyn = smem_addr32(smem_dyn);
    #pragma unroll
    for (int s = 0; s < STAGES; s++) {
        sA_base[s] = sdyn + (uint32_t)(s * TILE_HALVES) * 2u;
        sB_base[s] = sdyn + (uint32_t)((STAGES + s) * TILE_HALVES) * 2u;
    }

    // per-thread copy coords: idx = tid + j*256; row = idx>>2, chunk = idx&3
    int cp_row = tid >> 2;
    int cp_c   = (tid & 3) * 8;          // half offset of 16B chunk
    int cp_row2 = (tid + 256) >> 2;
    int cp_c2   = ((tid + 256) & 3) * 8;

    // ldmatrix coords
    int a_row = warp_m * 32 + (lane & 15);
    int a_colb = ((lane >> 4) << 3);
    int quad = lane >> 3;
    int b_row_off = ((quad >> 1) << 3) + (lane & 7);
    int b_colb = ((quad & 1) << 3);

    // Prologue: prefetch stages for kt=0,1
    #pragma unroll
    for (int p = 0; p < 2; p++) {
        int kb = p * BK;
        cp_async16(sA_base[p] + (cp_row  * SROW + cp_c ) * 2, gA + (size_t)cp_row  * DIM + kb + cp_c );
        cp_async16(sA_base[p] + (cp_row2 * SROW + cp_c2) * 2, gA + (size_t)cp_row2 * DIM + kb + cp_c2);
        cp_async16(sB_base[p] + (cp_row  * SROW + cp_c ) * 2, gB + (size_t)cp_row  * DIM + kb + cp_c );
        cp_async16(sB_base[p] + (cp_row2 * SROW + cp_c2) * 2, gB + (size_t)cp_row2 * DIM + kb + cp_c2);
        asm volatile("cp.async.commit_group;");
    }

    #pragma unroll 4
    for (int kt = 0; kt < NKT; kt++) {
        asm volatile("cp.async.wait_group 1;");
        __syncthreads();

        // prefetch kt+2 (always commit to keep group accounting uniform)
        if (kt + 2 < NKT) {
            int buf = (kt + 2) % STAGES;
            int kb = (kt + 2) * BK;
            cp_async16(sA_base[buf] + (cp_row  * SROW + cp_c ) * 2, gA + (size_t)cp_row  * DIM + kb + cp_c );
            cp_async16(sA_base[buf] + (cp_row2 * SROW + cp_c2) * 2, gA + (size_t)cp_row2 * DIM + kb + cp_c2);
            cp_async16(sB_base[buf] + (cp_row  * SROW + cp_c ) * 2, gB + (size_t)cp_row  * DIM + kb + cp_c );
            cp_async16(sB_base[buf] + (cp_row2 * SROW + cp_c2) * 2, gB + (size_t)cp_row2 * DIM + kb + cp_c2);
        }
        asm volatile("cp.async.commit_group;");

        int buf = kt % STAGES;
        #pragma unroll
        for (int ks = 0; ks < 2; ks++) {
            uint32_t af[2][4];
            #pragma unroll
            for (int mt = 0; mt < 2; mt++) {
                uint32_t addr = sA_base[buf] +
                    ((a_row + mt * 16) * SROW + ks * 16 + a_colb) * 2;
                ldmatrix_x4(af[mt][0], af[mt][1], af[mt][2], af[mt][3], addr);
            }
            uint32_t bf[8][2];
            #pragma unroll
            for (int ntp = 0; ntp < 4; ntp++) {
                uint32_t r0, r1, r2, r3;
                uint32_t addr = sB_base[buf] +
                    ((warp_n * 64 + ntp * 16 + b_row_off) * SROW + ks * 16 + b_colb) * 2;
                ldmatrix_x4(r0, r1, r2, r3, addr);
                bf[ntp * 2 + 0][0] = r0; bf[ntp * 2 + 0][1] = r1;
                bf[ntp * 2 + 1][0] = r2; bf[ntp * 2 + 1][1] = r3;
            }
            #pragma unroll
            for (int mt = 0; mt < 2; mt++)
                #pragma unroll
                for (int nt = 0; nt < 8; nt++)
                    mma16816(acc[mt][nt], af[mt], bf[nt]);
        }
    }

    // Epilogue: direct fragment stores with bias + ReLU.
    #pragma unroll
    for (int nt = 0; nt < 8; nt++) {
        int col = n0 + warp_n * 64 + nt * 8 + ((lane & 3) << 1);
        float b0 = bias[col], b1 = bias[col + 1];
        #pragma unroll
        for (int mt = 0; mt < 2; mt++) {
            int row = m0 + warp_m * 32 + mt * 16 + (lane >> 2);
            float2 v0, v1;
            v0.x = fmaxf(acc[mt][nt][0] + b0, 0.0f);
            v0.y = fmaxf(acc[mt][nt][1] + b1, 0.0f);
            v1.x = fmaxf(acc[mt][nt][2] + b0, 0.0f);
            v1.y = fmaxf(acc[mt][nt][3] + b1, 0.0f);
            *(float2*)(out + (size_t)row * ODIM + col) = v0;
            *(float2*)(out + (size_t)(row + 8) * ODIM + col) = v1;
        }
    }
}

// ---------------------------------------------------------------------------
// Launch
// ---------------------------------------------------------------------------
extern "C" void kernel_launch(void* const* d_in, const int* in_sizes, int n_in,
                              void* d_out, int out_size)
{
    const float* self_vecs = (const float*)d_in[0];   // [16384, 512]
    const float* neigh     = (const float*)d_in[1];   // [16384, 25, 512]
    // d_in[2] = temperature (unused by reference)
    const float* W         = (const float*)d_in[3];   // [512, 1024]
    const float* b         = (const float*)d_in[4];   // [1024]
    float* out = (float*)d_out;                       // [16384, 1024]

    static bool attr_set = false;
    if (!attr_set) {
        cudaFuncSetAttribute(gemm_kernel, cudaFuncAttributeMaxDynamicSharedMemorySize,
                             SMEM_BYTES);
        attr_set = true;
    }

    wprep_kernel<<<128, 256>>>(W);
    mean_kernel<<<N_ROWS, 128>>>(self_vecs, neigh);
    dim3 gg(N_ROWS / BM, ODIM / BN);
    gemm_kernel<<<gg, 256, SMEM_BYTES>>>(b, out);
}